// round 11
// baseline (speedup 1.0000x reference)
#include <cuda_runtime.h>

#define BN 128
#define PN 24564
#define ON 20
#define NCH 12
#define CH 2048            // k_match chunk: 12*2048 = 24576 >= PN (tail clamped)
#define LNCH 6
#define LCH 4096           // k_loss chunk: 6*4096 = 24576 >= PN
#define NPART (BN * LNCH)  // 768 partial slots
#define HB 0x3F000000u     // bits of 0.5f

// ---- scratch (static device globals; all fully rewritten every call) ----
__device__ unsigned      g_blockbo[BN * NCH * ON]; // per-(b,chunk,o) max iou bits
__device__ unsigned char g_match[BN * PN];         // bit0=pos, bit1=override, bits2+=idx(ovr)
__device__ float         g_pl[NPART], g_pc[NPART]; // per-block partial losses
__device__ int           g_pn[NPART];              // per-block positive counts

// ---- bit-deterministic IoU (shared by all kernels) ----
// _rn intrinsics block FFMA contraction => identical SASS DAG everywhere.
__device__ __forceinline__ void corners(float4 pr, float& x0, float& y0,
                                        float& x1, float& y1, float& ap) {
    float hx = __fmul_rn(pr.z, 0.5f), hy = __fmul_rn(pr.w, 0.5f);
    x0 = __fadd_rn(pr.x, -hx); y0 = __fadd_rn(pr.y, -hy);
    x1 = __fadd_rn(pr.x,  hx); y1 = __fadd_rn(pr.y,  hy);
    ap = __fmul_rn(__fadd_rn(x1, -x0), __fadd_rn(y1, -y0));
}
__device__ __forceinline__ unsigned iou_bits(float x0, float y0, float x1, float y1,
                                             float ap, float4 t, float sa) {
    float w = __fadd_rn(fminf(t.z, x1), -fmaxf(t.x, x0));
    float h = __fadd_rn(fminf(t.w, y1), -fmaxf(t.y, y0));
    w = fmaxf(w, 0.0f); h = fmaxf(h, 0.0f);
    float inter = __fmul_rn(w, h);
    float den   = __fadd_rn(__fadd_rn(sa, ap), -inter);
    float v     = __fdividef(inter, den);      // iou >= 0 -> bits monotonic
    return __float_as_uint(v);
}

// ---------------------------------------------------------------- matching (hot, proven 45.4us)
__global__ __launch_bounds__(256, 4)
void k_match(const float4* __restrict__ priors, const float* __restrict__ gt) {
    __shared__ float4   sbox[ON];
    __shared__ float    sarea[ON];
    __shared__ unsigned red[ON][8];

    const int b = blockIdx.y, cx = blockIdx.x, tid = threadIdx.x;
    if (tid < ON) {
        const float* g = gt + (b * ON + tid) * 5;
        float4 v = make_float4(g[0], g[1], g[2], g[3]);
        sbox[tid]  = v;
        sarea[tid] = __fmul_rn(__fadd_rn(v.z, -v.x), __fadd_rn(v.w, -v.y));
    }
    __syncthreads();

    unsigned bo[ON];
#pragma unroll
    for (int o = 0; o < ON; o++) bo[o] = 0u;

    const int p0 = cx * CH;
#pragma unroll 1
    for (int i = tid; i < CH / 2; i += 256) {
        int pA = p0 + i;
        int pB = pA + CH / 2;
        if (pB > PN - 1) pB = PN - 1;       // tail: duplicate evals, same value written
        float4 prA = __ldg(&priors[pA]);
        float4 prB = __ldg(&priors[pB]);
        float ax0, ay0, ax1, ay1, aA; corners(prA, ax0, ay0, ax1, ay1, aA);
        float bx0, by0, bx1, by1, aB; corners(prB, bx0, by0, bx1, by1, aB);

        unsigned mvA = 0u, mvB = 0u;
#pragma unroll
        for (int o = 0; o < ON; o++) {
            float4 t  = sbox[o];
            float  sa = sarea[o];
            unsigned vA = iou_bits(ax0, ay0, ax1, ay1, aA, t, sa);
            unsigned vB = iou_bits(bx0, by0, bx1, by1, aB, t, sa);
            mvA = max(mvA, vA);
            mvB = max(mvB, vB);
            bo[o] = max(bo[o], max(vA, vB));
        }
        g_match[b * PN + pA] = (unsigned char)(mvA >= HB);
        g_match[b * PN + pB] = (unsigned char)(mvB >= HB);
    }

    const int lane = tid & 31, wid = tid >> 5;
#pragma unroll
    for (int o = 0; o < ON; o++) {
        unsigned m = __reduce_max_sync(0xFFFFFFFFu, bo[o]);
        if (lane == 0) red[o][wid] = m;
    }
    __syncthreads();
    if (tid < ON) {
        unsigned m = red[tid][0];
#pragma unroll
        for (int w = 1; w < 8; w++) m = max(m, red[tid][w]);
        g_blockbo[(b * NCH + cx) * ON + tid] = m;
    }
}

// ---------------------------------------------------------------- findp + override (one block per image)
__global__ __launch_bounds__(256)
void k_findov(const float4* __restrict__ priors, const float* __restrict__ gt) {
    __shared__ unsigned sbestp[ON];
    const int b = blockIdx.x;
    const int tid = threadIdx.x, wid = tid >> 5, lane = tid & 31;

    for (int o = wid; o < ON; o += 8) {
        const float* g = gt + (b * ON + o) * 5;
        float4 t  = make_float4(g[0], g[1], g[2], g[3]);
        float  sa = __fmul_rn(__fadd_rn(t.z, -t.x), __fadd_rn(t.w, -t.y));

        unsigned M = 0u; int c = 0;
#pragma unroll
        for (int cc = NCH - 1; cc >= 0; cc--) {  // descending + >= : smallest chunk on ties
            unsigned v = g_blockbo[(b * NCH + cc) * ON + o];
            if (v >= M) { M = v; c = cc; }
        }

        unsigned minp = 0x7FFFFFFFu;
        for (int i = lane; i < CH; i += 32) {
            int p = c * CH + i;
            if (p < PN) {
                float4 pr = __ldg(&priors[p]);
                float x0, y0, x1, y1, ap; corners(pr, x0, y0, x1, y1, ap);
                if (iou_bits(x0, y0, x1, y1, ap, t, sa) == M)
                    minp = min(minp, (unsigned)p);   // smallest p among ties
            }
        }
        minp = __reduce_min_sync(0xFFFFFFFFu, minp);
        if (lane == 0) sbestp[o] = (minp == 0x7FFFFFFFu) ? 0u : minp;
    }
    __syncthreads();
    if (tid == 0) {
#pragma unroll
        for (int o = 0; o < ON; o++)             // serial ascending => last-o-wins
            g_match[b * PN + sbestp[o]] = (unsigned char)((o << 2) | 3);
    }
}

// ---------------------------------------------------------------- fused loss: compact -> idx+smoothL1 -> focal
__device__ __forceinline__ float smooth_l1(float d) {
    float ad = fabsf(d);
    return (ad < 1.0f) ? 0.5f * d * d : ad - 0.5f;
}
__device__ __forceinline__ float focal1(float c0, float c1, int cls) {
    float z  = c0 - c1;
    float s  = (cls == 1) ? -z : z;
    float e  = __expf(-s);
    float pc = __fdividef(1.0f, 1.0f + e);       // 2-class softmax via sigmoid
    pc = fminf(fmaxf(pc, 1e-7f), 1.0f - 1e-7f);
    float om = 1.0f - pc;
    float fl = 0.25f * (-__logf(pc)) * om * om;
    return (cls < 2) ? fl : 0.0f;
}

__global__ __launch_bounds__(256)
void k_loss(const float4* __restrict__ loc, const float4* __restrict__ conf4,
            const float4* __restrict__ priors, const float* __restrict__ gt) {
    __shared__ float4 sbox[ON];
    __shared__ float  sarea[ON];
    __shared__ int    slab[ON];
    __shared__ unsigned short slist[LCH];
    __shared__ unsigned char  scls[LCH];
    __shared__ int    scount;
    __shared__ float  swl[8], swc[8];

    const int b = blockIdx.y, cx = blockIdx.x, tid = threadIdx.x;
    const int lane = tid & 31;
    if (tid == 0) scount = 0;
    if (tid < ON) {
        const float* g = gt + (b * ON + tid) * 5;
        float4 v = make_float4(g[0], g[1], g[2], g[3]);
        sbox[tid]  = v;
        sarea[tid] = __fmul_rn(__fadd_rn(v.z, -v.x), __fadd_rn(v.w, -v.y));
        slab[tid]  = (int)g[4];
    }
    // zero the class table (uint-packed)
#pragma unroll
    for (int k = 0; k < LCH / 1024; k++)
        ((unsigned*)scls)[k * 256 + tid] = 0u;

    const int p0 = cx * LCH;

    // phase 1: ballot-compact positive prior offsets (uniform trips; needs g_match only)
    __syncthreads();
#pragma unroll 1
    for (int k = 0; k < LCH / 256; k++) {
        int i = k * 256 + tid;
        int p = p0 + i;
        bool pos = (p < PN) && (g_match[b * PN + p] & 1);
        unsigned msk = __ballot_sync(0xFFFFFFFFu, pos);
        if (msk) {
            int leader = __ffs(msk) - 1;
            int base = 0;
            if (lane == leader) base = atomicAdd(&scount, __popc(msk));
            base = __shfl_sync(0xFFFFFFFFu, base, leader);
            if (pos)
                slist[base + __popc(msk & ((1u << lane) - 1u))] = (unsigned short)i;
        }
    }
    __syncthreads();
    const int n = scount;

    // phase 2: dense over compacted positives (~100/block): idx recovery + smooth-L1
    float sl = 0.0f;
#pragma unroll 1
    for (int i = tid; i < n; i += 256) {
        int off = slist[i];
        int p   = p0 + off;
        int ix  = b * PN + p;
        unsigned char code = g_match[ix];
        float4 pr = __ldg(&priors[p]);
        int idx;
        if (code & 2) {
            idx = code >> 2;                       // overridden: forced GT
        } else {
            // bit-exact argmax recovery (first-o wins on ties)
            float x0, y0, x1, y1, ap; corners(pr, x0, y0, x1, y1, ap);
            unsigned best = 0u; idx = 0;
#pragma unroll
            for (int o = 0; o < ON; o++) {
                unsigned v = iou_bits(x0, y0, x1, y1, ap, sbox[o], sarea[o]);
                if (v > best) { best = v; idx = o; }
            }
        }
        scls[off] = (unsigned char)(slab[idx] + 1);

        float4 mb = sbox[idx];
        float4 ld = __ldg(&loc[ix]);
        float iw = __fdividef(1.0f, pr.z);
        float ih = __fdividef(1.0f, pr.w);
        float gx = ((mb.x + mb.z) * 0.5f - pr.x) * 10.0f * iw;
        float gy = ((mb.y + mb.w) * 0.5f - pr.y) * 10.0f * ih;
        float gw = __logf((mb.z - mb.x) * iw) * 5.0f;
        float gh = __logf((mb.w - mb.y) * ih) * 5.0f;
        sl += smooth_l1(ld.x - gx) + smooth_l1(ld.y - gy)
            + smooth_l1(ld.z - gw) + smooth_l1(ld.w - gh);
    }
    __syncthreads();

    // phase 3: focal over the chunk's priors, classes from smem
    float sc = 0.0f;
#pragma unroll
    for (int k = 0; k < LCH / 1024; k++) {
        int q = k * 256 + tid;                    // quad within chunk
        int p = p0 + q * 4;
        if (p < PN) {
            int ix = b * PN + p;
            uchar4 cls4 = ((const uchar4*)scls)[q];
            float4 ca = __ldg(&conf4[ix >> 1]);
            float4 cb = __ldg(&conf4[(ix >> 1) + 1]);
            sc += focal1(ca.x, ca.y, cls4.x) + focal1(ca.z, ca.w, cls4.y)
                + focal1(cb.x, cb.y, cls4.z) + focal1(cb.z, cb.w, cls4.w);
        }
    }

    // block reduction -> plain stores to per-block partial slots (no global atomics)
#pragma unroll
    for (int off = 16; off; off >>= 1) {
        sl += __shfl_down_sync(0xFFFFFFFFu, sl, off);
        sc += __shfl_down_sync(0xFFFFFFFFu, sc, off);
    }
    if (lane == 0) { swl[tid >> 5] = sl; swc[tid >> 5] = sc; }
    __syncthreads();
    if (tid == 0) {
        float tl = 0.0f, tc = 0.0f;
#pragma unroll
        for (int w = 0; w < 8; w++) { tl += swl[w]; tc += swc[w]; }
        int slot = b * LNCH + cx;
        g_pl[slot] = tl;
        g_pc[slot] = tc;
        g_pn[slot] = n;
    }
}

// ---------------------------------------------------------------- final reduction (768 partials, 1 block)
__global__ __launch_bounds__(256)
void k_final(float* out) {
    __shared__ double sdl[8], sdc[8];
    __shared__ int    sdn[8];
    const int tid = threadIdx.x, lane = tid & 31;

    double sl = 0.0, sc = 0.0; int n = 0;
    for (int i = tid; i < NPART; i += 256) {
        sl += (double)g_pl[i];
        sc += (double)g_pc[i];
        n  += g_pn[i];
    }
#pragma unroll
    for (int off = 16; off; off >>= 1) {
        sl += __shfl_down_sync(0xFFFFFFFFu, sl, off);
        sc += __shfl_down_sync(0xFFFFFFFFu, sc, off);
        n  += __shfl_down_sync(0xFFFFFFFFu, n, off);
    }
    if (lane == 0) { sdl[tid >> 5] = sl; sdc[tid >> 5] = sc; sdn[tid >> 5] = n; }
    __syncthreads();
    if (tid == 0) {
        double tl = 0.0, tc = 0.0; int tn = 0;
#pragma unroll
        for (int w = 0; w < 8; w++) { tl += sdl[w]; tc += sdc[w]; tn += sdn[w]; }
        double np = (double)tn;
        if (np < 1.0) np = 1.0;
        out[0] = (float)(tl / np);
        out[1] = (float)(tc / np);
    }
}

// ---------------------------------------------------------------- launch (4 graph nodes)
extern "C" void kernel_launch(void* const* d_in, const int* in_sizes, int n_in,
                              void* d_out, int out_size) {
    const float4* loc    = (const float4*)d_in[0];  // [B,P,4] f32
    const float4* conf4  = (const float4*)d_in[1];  // [B,P,2] f32 as float4 pairs
    const float4* priors = (const float4*)d_in[2];  // [P,4]   f32
    const float*  gt     = (const float*)d_in[3];   // [B,O,5] f32

    dim3 gm(NCH, BN);                       // 1536 blocks
    k_match<<<gm, 256>>>(priors, gt);

    k_findov<<<BN, 256>>>(priors, gt);      // 128 blocks

    dim3 gl(LNCH, BN);                      // 768 blocks
    k_loss<<<gl, 256>>>(loc, conf4, priors, gt);

    k_final<<<1, 256>>>((float*)d_out);
}

// round 12
// speedup vs baseline: 1.4247x; 1.4247x over previous
#include <cuda_runtime.h>

#define BN 128
#define PN 24564
#define ON 20
#define NCH 12
#define CH 2048            // k_match chunk: 12*2048 = 24576 >= PN (tail clamped)
#define LNCH 6
#define LCH 4096           // k_loss chunk: 6*4096 = 24576 >= PN
#define NPART (BN * LNCH)  // 768 partial slots
#define HB 0x3F000000u     // bits of 0.5f

// ---- scratch (static device globals; all fully rewritten every call) ----
__device__ unsigned      g_blockbo[BN * NCH * ON]; // per-(b,chunk,o) max iou bits
__device__ unsigned      g_bestp[BN * ON];         // per-(b,o) best prior index
__device__ unsigned char g_match[BN * PN];         // bit0=pos, bit1=override, bits2+=idx(ovr)
__device__ float         g_pl[NPART], g_pc[NPART]; // per-block partial losses
__device__ int           g_pn[NPART];              // per-block positive counts
__device__ unsigned      g_ctr;                    // loss-block completion counter

// ---- bit-deterministic IoU (shared by all kernels) ----
// _rn intrinsics block FFMA contraction => identical SASS DAG everywhere.
__device__ __forceinline__ void corners(float4 pr, float& x0, float& y0,
                                        float& x1, float& y1, float& ap) {
    float hx = __fmul_rn(pr.z, 0.5f), hy = __fmul_rn(pr.w, 0.5f);
    x0 = __fadd_rn(pr.x, -hx); y0 = __fadd_rn(pr.y, -hy);
    x1 = __fadd_rn(pr.x,  hx); y1 = __fadd_rn(pr.y,  hy);
    ap = __fmul_rn(__fadd_rn(x1, -x0), __fadd_rn(y1, -y0));
}
__device__ __forceinline__ unsigned iou_bits(float x0, float y0, float x1, float y1,
                                             float ap, float4 t, float sa) {
    float w = __fadd_rn(fminf(t.z, x1), -fmaxf(t.x, x0));
    float h = __fadd_rn(fminf(t.w, y1), -fmaxf(t.y, y0));
    w = fmaxf(w, 0.0f); h = fmaxf(h, 0.0f);
    float inter = __fmul_rn(w, h);
    float den   = __fadd_rn(__fadd_rn(sa, ap), -inter);
    float v     = __fdividef(inter, den);      // iou >= 0 -> bits monotonic
    return __float_as_uint(v);
}

// ---------------------------------------------------------------- matching (hot, proven 45.4us)
__global__ __launch_bounds__(256, 4)
void k_match(const float4* __restrict__ priors, const float* __restrict__ gt) {
    __shared__ float4   sbox[ON];
    __shared__ float    sarea[ON];
    __shared__ unsigned red[ON][8];

    const int b = blockIdx.y, cx = blockIdx.x, tid = threadIdx.x;
    if (b == 0 && cx == 0 && tid == 0) g_ctr = 0;    // reset loss-completion counter
    if (tid < ON) {
        const float* g = gt + (b * ON + tid) * 5;
        float4 v = make_float4(g[0], g[1], g[2], g[3]);
        sbox[tid]  = v;
        sarea[tid] = __fmul_rn(__fadd_rn(v.z, -v.x), __fadd_rn(v.w, -v.y));
    }
    __syncthreads();

    unsigned bo[ON];
#pragma unroll
    for (int o = 0; o < ON; o++) bo[o] = 0u;

    const int p0 = cx * CH;
#pragma unroll 1
    for (int i = tid; i < CH / 2; i += 256) {
        int pA = p0 + i;
        int pB = pA + CH / 2;
        if (pB > PN - 1) pB = PN - 1;       // tail: duplicate evals, same value written
        float4 prA = __ldg(&priors[pA]);
        float4 prB = __ldg(&priors[pB]);
        float ax0, ay0, ax1, ay1, aA; corners(prA, ax0, ay0, ax1, ay1, aA);
        float bx0, by0, bx1, by1, aB; corners(prB, bx0, by0, bx1, by1, aB);

        unsigned mvA = 0u, mvB = 0u;
#pragma unroll
        for (int o = 0; o < ON; o++) {
            float4 t  = sbox[o];
            float  sa = sarea[o];
            unsigned vA = iou_bits(ax0, ay0, ax1, ay1, aA, t, sa);
            unsigned vB = iou_bits(bx0, by0, bx1, by1, aB, t, sa);
            mvA = max(mvA, vA);
            mvB = max(mvB, vB);
            bo[o] = max(bo[o], max(vA, vB));
        }
        g_match[b * PN + pA] = (unsigned char)(mvA >= HB);
        g_match[b * PN + pB] = (unsigned char)(mvB >= HB);
    }

    const int lane = tid & 31, wid = tid >> 5;
#pragma unroll
    for (int o = 0; o < ON; o++) {
        unsigned m = __reduce_max_sync(0xFFFFFFFFu, bo[o]);
        if (lane == 0) red[o][wid] = m;
    }
    __syncthreads();
    if (tid < ON) {
        unsigned m = red[tid][0];
#pragma unroll
        for (int w = 1; w < 8; w++) m = max(m, red[tid][w]);
        g_blockbo[(b * NCH + cx) * ON + tid] = m;
    }
}

// ---------------------------------------------------------------- find best prior per (b,o): parallel rescan (R8-proven)
__global__ __launch_bounds__(256)
void k_findp(const float4* __restrict__ priors, const float* __restrict__ gt) {
    __shared__ unsigned sred[8];
    const int bo_ = blockIdx.x;
    const int b = bo_ / ON, o = bo_ % ON;
    const int tid = threadIdx.x;

    const float* g = gt + (b * ON + o) * 5;
    float4 t  = make_float4(g[0], g[1], g[2], g[3]);
    float  sa = __fmul_rn(__fadd_rn(t.z, -t.x), __fadd_rn(t.w, -t.y));

    unsigned M = 0u; int c = 0;
#pragma unroll
    for (int cc = NCH - 1; cc >= 0; cc--) {      // descending + >= : smallest chunk wins ties
        unsigned v = g_blockbo[(b * NCH + cc) * ON + o];
        if (v >= M) { M = v; c = cc; }
    }

    unsigned minp = 0x7FFFFFFFu;
#pragma unroll
    for (int k = 0; k < CH / 256; k++) {         // 8 independent iterations -> pipelined
        int p = c * CH + k * 256 + tid;
        if (p < PN) {
            float4 pr = __ldg(&priors[p]);
            float x0, y0, x1, y1, ap; corners(pr, x0, y0, x1, y1, ap);
            if (iou_bits(x0, y0, x1, y1, ap, t, sa) == M)
                minp = min(minp, (unsigned)p);   // smallest p among ties
        }
    }
    minp = __reduce_min_sync(0xFFFFFFFFu, minp);
    if ((tid & 31) == 0) sred[tid >> 5] = minp;
    __syncthreads();
    if (tid == 0) {
        unsigned m = sred[0];
#pragma unroll
        for (int w = 1; w < 8; w++) m = min(m, sred[w]);
        if (m == 0x7FFFFFFFu) m = 0;             // safety (bit-exact => unreachable)
        g_bestp[b * ON + o] = m;
    }
}

// ---------------------------------------------------------------- override: serial per image => last-o-wins
__global__ void k_override() {
    int b = blockIdx.x, lane = threadIdx.x;
    unsigned p = (lane < ON) ? g_bestp[b * ON + lane] : 0u;
#pragma unroll
    for (int o = 0; o < ON; o++) {
        unsigned pv = __shfl_sync(0xFFFFFFFFu, p, o);
        if (lane == 0)
            g_match[b * PN + pv] = (unsigned char)((o << 2) | 3);
    }
}

// ---------------------------------------------------------------- fused loss + device-side final reduction
__device__ __forceinline__ float smooth_l1(float d) {
    float ad = fabsf(d);
    return (ad < 1.0f) ? 0.5f * d * d : ad - 0.5f;
}
__device__ __forceinline__ float focal1(float c0, float c1, int cls) {
    float z  = c0 - c1;
    float s  = (cls == 1) ? -z : z;
    float e  = __expf(-s);
    float pc = __fdividef(1.0f, 1.0f + e);       // 2-class softmax via sigmoid
    pc = fminf(fmaxf(pc, 1e-7f), 1.0f - 1e-7f);
    float om = 1.0f - pc;
    float fl = 0.25f * (-__logf(pc)) * om * om;
    return (cls < 2) ? fl : 0.0f;
}

__global__ __launch_bounds__(256)
void k_loss(const float4* __restrict__ loc, const float4* __restrict__ conf4,
            const float4* __restrict__ priors, const float* __restrict__ gt,
            float* __restrict__ out) {
    __shared__ float4 sbox[ON];
    __shared__ float  sarea[ON];
    __shared__ int    slab[ON];
    __shared__ unsigned short slist[LCH];
    __shared__ unsigned char  scls[LCH];
    __shared__ int    scount;
    __shared__ float  swl[8], swc[8];
    __shared__ int    sIsLast;

    const int b = blockIdx.y, cx = blockIdx.x, tid = threadIdx.x;
    const int lane = tid & 31;
    if (tid == 0) { scount = 0; sIsLast = 0; }
    if (tid < ON) {
        const float* g = gt + (b * ON + tid) * 5;
        float4 v = make_float4(g[0], g[1], g[2], g[3]);
        sbox[tid]  = v;
        sarea[tid] = __fmul_rn(__fadd_rn(v.z, -v.x), __fadd_rn(v.w, -v.y));
        slab[tid]  = (int)g[4];
    }
    // zero the class table (uint-packed)
#pragma unroll
    for (int k = 0; k < LCH / 1024; k++)
        ((unsigned*)scls)[k * 256 + tid] = 0u;

    const int p0 = cx * LCH;

    // phase 1: ballot-compact positive prior offsets (uniform trips)
    __syncthreads();
#pragma unroll 1
    for (int k = 0; k < LCH / 256; k++) {
        int i = k * 256 + tid;
        int p = p0 + i;
        bool pos = (p < PN) && (g_match[b * PN + p] & 1);
        unsigned msk = __ballot_sync(0xFFFFFFFFu, pos);
        if (msk) {
            int leader = __ffs(msk) - 1;
            int base = 0;
            if (lane == leader) base = atomicAdd(&scount, __popc(msk));
            base = __shfl_sync(0xFFFFFFFFu, base, leader);
            if (pos)
                slist[base + __popc(msk & ((1u << lane) - 1u))] = (unsigned short)i;
        }
    }
    __syncthreads();
    const int n = scount;

    // phase 2: dense over compacted positives: idx recovery + smooth-L1
    float sl = 0.0f;
#pragma unroll 1
    for (int i = tid; i < n; i += 256) {
        int off = slist[i];
        int p   = p0 + off;
        int ix  = b * PN + p;
        unsigned char code = g_match[ix];
        float4 pr = __ldg(&priors[p]);
        int idx;
        if (code & 2) {
            idx = code >> 2;                       // overridden: forced GT
        } else {
            // bit-exact argmax recovery (first-o wins on ties)
            float x0, y0, x1, y1, ap; corners(pr, x0, y0, x1, y1, ap);
            unsigned best = 0u; idx = 0;
#pragma unroll
            for (int o = 0; o < ON; o++) {
                unsigned v = iou_bits(x0, y0, x1, y1, ap, sbox[o], sarea[o]);
                if (v > best) { best = v; idx = o; }
            }
        }
        scls[off] = (unsigned char)(slab[idx] + 1);

        float4 mb = sbox[idx];
        float4 ld = __ldg(&loc[ix]);
        float iw = __fdividef(1.0f, pr.z);
        float ih = __fdividef(1.0f, pr.w);
        float gx = ((mb.x + mb.z) * 0.5f - pr.x) * 10.0f * iw;
        float gy = ((mb.y + mb.w) * 0.5f - pr.y) * 10.0f * ih;
        float gw = __logf((mb.z - mb.x) * iw) * 5.0f;
        float gh = __logf((mb.w - mb.y) * ih) * 5.0f;
        sl += smooth_l1(ld.x - gx) + smooth_l1(ld.y - gy)
            + smooth_l1(ld.z - gw) + smooth_l1(ld.w - gh);
    }
    __syncthreads();

    // phase 3: focal over the chunk's priors, classes from smem
    float sc = 0.0f;
#pragma unroll
    for (int k = 0; k < LCH / 1024; k++) {
        int q = k * 256 + tid;                    // quad within chunk
        int p = p0 + q * 4;
        if (p < PN) {
            int ix = b * PN + p;
            uchar4 cls4 = ((const uchar4*)scls)[q];
            float4 ca = __ldg(&conf4[ix >> 1]);
            float4 cb = __ldg(&conf4[(ix >> 1) + 1]);
            sc += focal1(ca.x, ca.y, cls4.x) + focal1(ca.z, ca.w, cls4.y)
                + focal1(cb.x, cb.y, cls4.z) + focal1(cb.z, cb.w, cls4.w);
        }
    }

    // block reduction -> plain stores to per-block slots (no contended atomics)
#pragma unroll
    for (int off = 16; off; off >>= 1) {
        sl += __shfl_down_sync(0xFFFFFFFFu, sl, off);
        sc += __shfl_down_sync(0xFFFFFFFFu, sc, off);
    }
    if (lane == 0) { swl[tid >> 5] = sl; swc[tid >> 5] = sc; }
    __syncthreads();
    if (tid == 0) {
        float tl = 0.0f, tc = 0.0f;
#pragma unroll
        for (int w = 0; w < 8; w++) { tl += swl[w]; tc += swc[w]; }
        int slot = b * LNCH + cx;
        g_pl[slot] = tl;
        g_pc[slot] = tc;
        g_pn[slot] = n;
        __threadfence();                           // make partials visible device-wide
        unsigned done = atomicAdd(&g_ctr, 1u);     // RMW total order
        sIsLast = (done == NPART - 1);
    }
    __syncthreads();

    // last block performs the final reduction (reads bypass L1 via __ldcg)
    if (sIsLast) {
        double dl = 0.0, dc = 0.0; int dn = 0;
        for (int i = tid; i < NPART; i += 256) {
            dl += (double)__ldcg(&g_pl[i]);
            dc += (double)__ldcg(&g_pc[i]);
            dn += __ldcg(&g_pn[i]);
        }
#pragma unroll
        for (int off = 16; off; off >>= 1) {
            dl += __shfl_down_sync(0xFFFFFFFFu, dl, off);
            dc += __shfl_down_sync(0xFFFFFFFFu, dc, off);
            dn += __shfl_down_sync(0xFFFFFFFFu, dn, off);
        }
        __shared__ double sdl[8], sdc[8];
        __shared__ int    sdn[8];
        if (lane == 0) { sdl[tid >> 5] = dl; sdc[tid >> 5] = dc; sdn[tid >> 5] = dn; }
        __syncthreads();
        if (tid == 0) {
            double tl = 0.0, tc = 0.0; int tn = 0;
#pragma unroll
            for (int w = 0; w < 8; w++) { tl += sdl[w]; tc += sdc[w]; tn += sdn[w]; }
            double np = (double)tn;
            if (np < 1.0) np = 1.0;
            out[0] = (float)(tl / np);
            out[1] = (float)(tc / np);
        }
    }
}

// ---------------------------------------------------------------- launch (4 graph nodes)
extern "C" void kernel_launch(void* const* d_in, const int* in_sizes, int n_in,
                              void* d_out, int out_size) {
    const float4* loc    = (const float4*)d_in[0];  // [B,P,4] f32
    const float4* conf4  = (const float4*)d_in[1];  // [B,P,2] f32 as float4 pairs
    const float4* priors = (const float4*)d_in[2];  // [P,4]   f32
    const float*  gt     = (const float*)d_in[3];   // [B,O,5] f32

    dim3 gm(NCH, BN);                       // 1536 blocks
    k_match<<<gm, 256>>>(priors, gt);

    k_findp<<<BN * ON, 256>>>(priors, gt);  // 2560 blocks, parallel rescan

    k_override<<<BN, 32>>>();               // 128 warps, last-o-wins

    dim3 gl(LNCH, BN);                      // 768 blocks; last one writes d_out
    k_loss<<<gl, 256>>>(loc, conf4, priors, gt, (float*)d_out);
}

// round 15
// speedup vs baseline: 1.4598x; 1.0247x over previous
// MultiBoxLoss GB300 — R15.
// Post-mortem R13/R14: R13 trapped on a uint4 load of g_match (b*PN is only
// 4-byte aligned since PN%16==4); R14 failed because prose leaked into the .cu.
// This round: R12 pipeline with the g_match codes loaded as four independent
// aligned 32-bit words (same MLP, no trap).
// Pipeline: k_match (proven 45.4us) -> k_findp (parallel rescan) -> k_override
// -> k_loss (phase A: 16 priors/thread bulk focal cls=0 + warp-scan compaction;
// phase B: sparse positives with bit-exact idx recovery + smooth-L1 + focal
// correction focal(cls)-focal(0); last block reduces 768 partials to d_out).
// Prediction: k_loss 38 -> ~10-13us (DRAM >=30%, issue >=50%); total -> ~62-68us.

#include <cuda_runtime.h>

#define BN 128
#define PN 24564
#define ON 20
#define NCH 12
#define CH 2048            // k_match chunk: 12*2048 = 24576 >= PN (tail clamped)
#define LNCH 6
#define LCH 4096           // k_loss chunk: 6*4096 = 24576 >= PN; 256 thr * 16 = 4096
#define NPART (BN * LNCH)  // 768 partial slots
#define HB 0x3F000000u     // bits of 0.5f

// ---- scratch (static device globals; all fully rewritten every call) ----
__device__ unsigned      g_blockbo[BN * NCH * ON]; // per-(b,chunk,o) max iou bits
__device__ unsigned      g_bestp[BN * ON];         // per-(b,o) best prior index
__device__ unsigned char g_match[BN * PN];         // bit0=pos, bit1=override, bits2+=idx(ovr)
__device__ float         g_pl[NPART], g_pc[NPART]; // per-block partial losses
__device__ int           g_pn[NPART];              // per-block positive counts
__device__ unsigned      g_ctr;                    // loss-block completion counter

// ---- bit-deterministic IoU (shared by all kernels) ----
// _rn intrinsics block FFMA contraction => identical SASS DAG everywhere.
__device__ __forceinline__ void corners(float4 pr, float& x0, float& y0,
                                        float& x1, float& y1, float& ap) {
    float hx = __fmul_rn(pr.z, 0.5f), hy = __fmul_rn(pr.w, 0.5f);
    x0 = __fadd_rn(pr.x, -hx); y0 = __fadd_rn(pr.y, -hy);
    x1 = __fadd_rn(pr.x,  hx); y1 = __fadd_rn(pr.y,  hy);
    ap = __fmul_rn(__fadd_rn(x1, -x0), __fadd_rn(y1, -y0));
}
__device__ __forceinline__ unsigned iou_bits(float x0, float y0, float x1, float y1,
                                             float ap, float4 t, float sa) {
    float w = __fadd_rn(fminf(t.z, x1), -fmaxf(t.x, x0));
    float h = __fadd_rn(fminf(t.w, y1), -fmaxf(t.y, y0));
    w = fmaxf(w, 0.0f); h = fmaxf(h, 0.0f);
    float inter = __fmul_rn(w, h);
    float den   = __fadd_rn(__fadd_rn(sa, ap), -inter);
    float v     = __fdividef(inter, den);      // iou >= 0 -> bits monotonic
    return __float_as_uint(v);
}

// ---------------------------------------------------------------- matching (hot, proven 45.4us)
__global__ __launch_bounds__(256, 4)
void k_match(const float4* __restrict__ priors, const float* __restrict__ gt) {
    __shared__ float4   sbox[ON];
    __shared__ float    sarea[ON];
    __shared__ unsigned red[ON][8];

    const int b = blockIdx.y, cx = blockIdx.x, tid = threadIdx.x;
    if (b == 0 && cx == 0 && tid == 0) g_ctr = 0;    // reset loss-completion counter
    if (tid < ON) {
        const float* g = gt + (b * ON + tid) * 5;
        float4 v = make_float4(g[0], g[1], g[2], g[3]);
        sbox[tid]  = v;
        sarea[tid] = __fmul_rn(__fadd_rn(v.z, -v.x), __fadd_rn(v.w, -v.y));
    }
    __syncthreads();

    unsigned bo[ON];
#pragma unroll
    for (int o = 0; o < ON; o++) bo[o] = 0u;

    const int p0 = cx * CH;
#pragma unroll 1
    for (int i = tid; i < CH / 2; i += 256) {
        int pA = p0 + i;
        int pB = pA + CH / 2;
        if (pB > PN - 1) pB = PN - 1;       // tail: duplicate evals, same value written
        float4 prA = __ldg(&priors[pA]);
        float4 prB = __ldg(&priors[pB]);
        float ax0, ay0, ax1, ay1, aA; corners(prA, ax0, ay0, ax1, ay1, aA);
        float bx0, by0, bx1, by1, aB; corners(prB, bx0, by0, bx1, by1, aB);

        unsigned mvA = 0u, mvB = 0u;
#pragma unroll
        for (int o = 0; o < ON; o++) {
            float4 t  = sbox[o];
            float  sa = sarea[o];
            unsigned vA = iou_bits(ax0, ay0, ax1, ay1, aA, t, sa);
            unsigned vB = iou_bits(bx0, by0, bx1, by1, aB, t, sa);
            mvA = max(mvA, vA);
            mvB = max(mvB, vB);
            bo[o] = max(bo[o], max(vA, vB));
        }
        g_match[b * PN + pA] = (unsigned char)(mvA >= HB);
        g_match[b * PN + pB] = (unsigned char)(mvB >= HB);
    }

    const int lane = tid & 31, wid = tid >> 5;
#pragma unroll
    for (int o = 0; o < ON; o++) {
        unsigned m = __reduce_max_sync(0xFFFFFFFFu, bo[o]);
        if (lane == 0) red[o][wid] = m;
    }
    __syncthreads();
    if (tid < ON) {
        unsigned m = red[tid][0];
#pragma unroll
        for (int w = 1; w < 8; w++) m = max(m, red[tid][w]);
        g_blockbo[(b * NCH + cx) * ON + tid] = m;
    }
}

// ---------------------------------------------------------------- find best prior per (b,o): parallel rescan
__global__ __launch_bounds__(256)
void k_findp(const float4* __restrict__ priors, const float* __restrict__ gt) {
    __shared__ unsigned sred[8];
    const int bo_ = blockIdx.x;
    const int b = bo_ / ON, o = bo_ % ON;
    const int tid = threadIdx.x;

    const float* g = gt + (b * ON + o) * 5;
    float4 t  = make_float4(g[0], g[1], g[2], g[3]);
    float  sa = __fmul_rn(__fadd_rn(t.z, -t.x), __fadd_rn(t.w, -t.y));

    unsigned M = 0u; int c = 0;
#pragma unroll
    for (int cc = NCH - 1; cc >= 0; cc--) {      // descending + >= : smallest chunk wins ties
        unsigned v = g_blockbo[(b * NCH + cc) * ON + o];
        if (v >= M) { M = v; c = cc; }
    }

    unsigned minp = 0x7FFFFFFFu;
#pragma unroll
    for (int k = 0; k < CH / 256; k++) {         // 8 independent iterations -> pipelined
        int p = c * CH + k * 256 + tid;
        if (p < PN) {
            float4 pr = __ldg(&priors[p]);
            float x0, y0, x1, y1, ap; corners(pr, x0, y0, x1, y1, ap);
            if (iou_bits(x0, y0, x1, y1, ap, t, sa) == M)
                minp = min(minp, (unsigned)p);   // smallest p among ties
        }
    }
    minp = __reduce_min_sync(0xFFFFFFFFu, minp);
    if ((tid & 31) == 0) sred[tid >> 5] = minp;
    __syncthreads();
    if (tid == 0) {
        unsigned m = sred[0];
#pragma unroll
        for (int w = 1; w < 8; w++) m = min(m, sred[w]);
        if (m == 0x7FFFFFFFu) m = 0;             // safety (bit-exact => unreachable)
        g_bestp[b * ON + o] = m;
    }
}

// ---------------------------------------------------------------- override: serial per image => last-o-wins
__global__ void k_override() {
    int b = blockIdx.x, lane = threadIdx.x;
    unsigned p = (lane < ON) ? g_bestp[b * ON + lane] : 0u;
#pragma unroll
    for (int o = 0; o < ON; o++) {
        unsigned pv = __shfl_sync(0xFFFFFFFFu, p, o);
        if (lane == 0)
            g_match[b * PN + pv] = (unsigned char)((o << 2) | 3);
    }
}

// ---------------------------------------------------------------- fused loss + device-side final reduction
__device__ __forceinline__ float smooth_l1(float d) {
    float ad = fabsf(d);
    return (ad < 1.0f) ? 0.5f * d * d : ad - 0.5f;
}
__device__ __forceinline__ float focal1(float c0, float c1, int cls) {
    float z  = c0 - c1;
    float s  = (cls == 1) ? -z : z;
    float e  = __expf(-s);
    float pc = __fdividef(1.0f, 1.0f + e);       // 2-class softmax via sigmoid
    pc = fminf(fmaxf(pc, 1e-7f), 1.0f - 1e-7f);
    float om = 1.0f - pc;
    float fl = 0.25f * (-__logf(pc)) * om * om;
    return (cls < 2) ? fl : 0.0f;
}
__device__ __forceinline__ float focal_bg(float c0, float c1) {  // cls = 0 path
    float e  = __expf(c1 - c0);
    float pc = __fdividef(1.0f, 1.0f + e);
    pc = fminf(fmaxf(pc, 1e-7f), 1.0f - 1e-7f);
    float om = 1.0f - pc;
    return 0.25f * (-__logf(pc)) * om * om;
}

__global__ __launch_bounds__(256)
void k_loss(const float4* __restrict__ loc, const float4* __restrict__ conf4,
            const float4* __restrict__ priors, const float* __restrict__ gt,
            float* __restrict__ out) {
    __shared__ float4 sbox[ON];
    __shared__ float  sarea[ON];
    __shared__ int    slab[ON];
    __shared__ unsigned short slist[LCH];
    __shared__ int    scount;
    __shared__ float  swl[8], swc[8];
    __shared__ int    sIsLast;

    const int b = blockIdx.y, cx = blockIdx.x, tid = threadIdx.x;
    const int lane = tid & 31;
    if (tid == 0) { scount = 0; sIsLast = 0; }
    if (tid < ON) {
        const float* g = gt + (b * ON + tid) * 5;
        float4 v = make_float4(g[0], g[1], g[2], g[3]);
        sbox[tid]  = v;
        sarea[tid] = __fmul_rn(__fadd_rn(v.z, -v.x), __fadd_rn(v.w, -v.y));
        slab[tid]  = (int)g[4];
    }
    __syncthreads();

    const int p0    = cx * LCH;
    const int pbase = p0 + tid * 16;          // 16 consecutive priors per thread

    // ---- phase A: bulk focal (cls=0) + single-round compaction, high MLP ----
    float sc = 0.0f;
    unsigned codes[4];
    const bool tail = (pbase + 16 > PN);      // only last chunk threads
    if (!tail) {
        // b*PN is 4-byte aligned only (PN % 16 == 4) -> four independent LDG.32
        const unsigned* cwp = (const unsigned*)&g_match[b * PN + pbase];
        codes[0] = cwp[0]; codes[1] = cwp[1]; codes[2] = cwp[2]; codes[3] = cwp[3];
    } else {
#pragma unroll
        for (int j = 0; j < 4; j++) {
            unsigned w = 0;
#pragma unroll
            for (int k = 0; k < 4; k++) {
                int p = pbase + j * 4 + k;
                unsigned char cb = (p < PN) ? g_match[b * PN + p] : 0;
                w |= (unsigned)cb << (8 * k);
            }
            codes[j] = w;
        }
    }

    if (!tail) {
        const float4* cbase = conf4 + ((long long)b * PN + pbase) / 2;
#pragma unroll
        for (int j = 0; j < 8; j++) {          // 8 independent LDG.128
            float4 c = __ldg(&cbase[j]);
            sc += focal_bg(c.x, c.y) + focal_bg(c.z, c.w);
        }
    } else {
        const float* cf = (const float*)conf4;
#pragma unroll
        for (int k = 0; k < 16; k++) {
            int p = pbase + k;
            if (p < PN) {
                long long ix2 = ((long long)b * PN + p) * 2;
                sc += focal_bg(cf[ix2], cf[ix2 + 1]);
            }
        }
    }

    // compaction: warp inclusive scan of per-thread positive counts, <=1 atomic/warp
    int cnt = __popc(codes[0] & 0x01010101u) + __popc(codes[1] & 0x01010101u)
            + __popc(codes[2] & 0x01010101u) + __popc(codes[3] & 0x01010101u);
    int pre = cnt;
#pragma unroll
    for (int off = 1; off < 32; off <<= 1) {
        int v = __shfl_up_sync(0xFFFFFFFFu, pre, off);
        if (lane >= off) pre += v;
    }
    int wtotal = __shfl_sync(0xFFFFFFFFu, pre, 31);
    if (wtotal) {
        int wbase = 0;
        if (lane == 31) wbase = atomicAdd(&scount, wtotal);
        wbase = __shfl_sync(0xFFFFFFFFu, wbase, 31);
        int mybase = wbase + pre - cnt;
        if (cnt) {
            int w = 0;
#pragma unroll
            for (int j = 0; j < 4; j++)
#pragma unroll
                for (int k = 0; k < 4; k++)
                    if ((codes[j] >> (8 * k)) & 1)
                        slist[mybase + w++] = (unsigned short)(tid * 16 + j * 4 + k);
        }
    }
    __syncthreads();
    const int n = scount;

    // ---- phase B: dense positives: idx recovery + smooth-L1 + focal correction ----
    float sl = 0.0f;
#pragma unroll 1
    for (int i = tid; i < n; i += 256) {
        int off = slist[i];
        int p   = p0 + off;
        long long ix = (long long)b * PN + p;
        unsigned char code = g_match[ix];
        float4 pr = __ldg(&priors[p]);
        int idx;
        if (code & 2) {
            idx = code >> 2;                       // overridden: forced GT
        } else {
            // bit-exact argmax recovery (first-o wins on ties)
            float x0, y0, x1, y1, ap; corners(pr, x0, y0, x1, y1, ap);
            unsigned best = 0u; idx = 0;
#pragma unroll
            for (int o = 0; o < ON; o++) {
                unsigned v = iou_bits(x0, y0, x1, y1, ap, sbox[o], sarea[o]);
                if (v > best) { best = v; idx = o; }
            }
        }
        int cls = slab[idx] + 1;

        // focal correction: replace the cls=0 base term with the true class
        float2 cd = __ldg(&((const float2*)conf4)[ix]);
        sc += focal1(cd.x, cd.y, cls) - focal_bg(cd.x, cd.y);

        float4 mb = sbox[idx];
        float4 ld = __ldg(&loc[ix]);
        float iw = __fdividef(1.0f, pr.z);
        float ih = __fdividef(1.0f, pr.w);
        float gx = ((mb.x + mb.z) * 0.5f - pr.x) * 10.0f * iw;
        float gy = ((mb.y + mb.w) * 0.5f - pr.y) * 10.0f * ih;
        float gw = __logf((mb.z - mb.x) * iw) * 5.0f;
        float gh = __logf((mb.w - mb.y) * ih) * 5.0f;
        sl += smooth_l1(ld.x - gx) + smooth_l1(ld.y - gy)
            + smooth_l1(ld.z - gw) + smooth_l1(ld.w - gh);
    }

    // block reduction -> plain stores to per-block slots (no contended atomics)
#pragma unroll
    for (int off = 16; off; off >>= 1) {
        sl += __shfl_down_sync(0xFFFFFFFFu, sl, off);
        sc += __shfl_down_sync(0xFFFFFFFFu, sc, off);
    }
    if (lane == 0) { swl[tid >> 5] = sl; swc[tid >> 5] = sc; }
    __syncthreads();
    if (tid == 0) {
        float tl = 0.0f, tc = 0.0f;
#pragma unroll
        for (int w = 0; w < 8; w++) { tl += swl[w]; tc += swc[w]; }
        int slot = b * LNCH + cx;
        g_pl[slot] = tl;
        g_pc[slot] = tc;
        g_pn[slot] = n;
        __threadfence();                           // make partials visible device-wide
        unsigned done = atomicAdd(&g_ctr, 1u);     // RMW total order
        sIsLast = (done == NPART - 1);
    }
    __syncthreads();

    // last block performs the final reduction (reads bypass L1 via __ldcg)
    if (sIsLast) {
        double dl = 0.0, dc = 0.0; int dn = 0;
        for (int i = tid; i < NPART; i += 256) {
            dl += (double)__ldcg(&g_pl[i]);
            dc += (double)__ldcg(&g_pc[i]);
            dn += __ldcg(&g_pn[i]);
        }
#pragma unroll
        for (int off = 16; off; off >>= 1) {
            dl += __shfl_down_sync(0xFFFFFFFFu, dl, off);
            dc += __shfl_down_sync(0xFFFFFFFFu, dc, off);
            dn += __shfl_down_sync(0xFFFFFFFFu, dn, off);
        }
        __shared__ double sdl[8], sdc[8];
        __shared__ int    sdn[8];
        if (lane == 0) { sdl[tid >> 5] = dl; sdc[tid >> 5] = dc; sdn[tid >> 5] = dn; }
        __syncthreads();
        if (tid == 0) {
            double tl = 0.0, tc = 0.0; int tn = 0;
#pragma unroll
            for (int w = 0; w < 8; w++) { tl += sdl[w]; tc += sdc[w]; tn += sdn[w]; }
            double np = (double)tn;
            if (np < 1.0) np = 1.0;
            out[0] = (float)(tl / np);
            out[1] = (float)(tc / np);
        }
    }
}

// ---------------------------------------------------------------- launch (4 graph nodes)
extern "C" void kernel_launch(void* const* d_in, const int* in_sizes, int n_in,
                              void* d_out, int out_size) {
    const float4* loc    = (const float4*)d_in[0];  // [B,P,4] f32
    const float4* conf4  = (const float4*)d_in[1];  // [B,P,2] f32 as float4 pairs
    const float4* priors = (const float4*)d_in[2];  // [P,4]   f32
    const float*  gt     = (const float*)d_in[3];   // [B,O,5] f32

    dim3 gm(NCH, BN);                       // 1536 blocks
    k_match<<<gm, 256>>>(priors, gt);

    k_findp<<<BN * ON, 256>>>(priors, gt);  // 2560 blocks, parallel rescan

    k_override<<<BN, 32>>>();               // 128 warps, last-o-wins

    dim3 gl(LNCH, BN);                      // 768 blocks; last one writes d_out
    k_loss<<<gl, 256>>>(loc, conf4, priors, gt, (float*)d_out);
}

// round 16
// speedup vs baseline: 1.4998x; 1.0274x over previous
// MultiBoxLoss GB300 - R16.
// R15 post-mortem: k_loss (29.2us) was latency/tail-bound with compute+DRAM
// floors ~3us each; k_match runs at DRAM 0.1%. This round the bulk focal
// (cls=0) over ALL priors moves into k_match (conf stream overlaps the idle
// DRAM under the IoU compute, +~6% instructions), and k_loss shrinks to a
// 3MB g_match scan + sparse positive processing + device-side final reduce.
// Prediction: k_match ~48-49us, k_loss ~5us, total ~60-64us.

#include <cuda_runtime.h>

#define BN 128
#define PN 24564
#define ON 20
#define NCH 12
#define CH 2048            // chunk for both k_match and k_loss: 12*2048 >= PN
#define NPART (BN * NCH)   // 1536 partial slots per kernel
#define HB 0x3F000000u     // bits of 0.5f

// ---- scratch (static device globals; all fully rewritten every call) ----
__device__ unsigned      g_blockbo[BN * NCH * ON]; // per-(b,chunk,o) max iou bits
__device__ unsigned      g_bestp[BN * ON];         // per-(b,o) best prior index
__device__ unsigned char g_match[BN * PN];         // bit0=pos, bit1=override, bits2+=idx(ovr)
__device__ float         g_pf[NPART];              // bulk-focal partials (k_match)
__device__ float         g_pl[NPART], g_pc[NPART]; // smoothL1 / focal-correction partials
__device__ int           g_pn[NPART];              // positive counts
__device__ unsigned      g_ctr;                    // k_loss completion counter

// ---- bit-deterministic IoU (shared by all kernels) ----
// _rn intrinsics block FFMA contraction => identical SASS DAG everywhere.
__device__ __forceinline__ void corners(float4 pr, float& x0, float& y0,
                                        float& x1, float& y1, float& ap) {
    float hx = __fmul_rn(pr.z, 0.5f), hy = __fmul_rn(pr.w, 0.5f);
    x0 = __fadd_rn(pr.x, -hx); y0 = __fadd_rn(pr.y, -hy);
    x1 = __fadd_rn(pr.x,  hx); y1 = __fadd_rn(pr.y,  hy);
    ap = __fmul_rn(__fadd_rn(x1, -x0), __fadd_rn(y1, -y0));
}
__device__ __forceinline__ unsigned iou_bits(float x0, float y0, float x1, float y1,
                                             float ap, float4 t, float sa) {
    float w = __fadd_rn(fminf(t.z, x1), -fmaxf(t.x, x0));
    float h = __fadd_rn(fminf(t.w, y1), -fmaxf(t.y, y0));
    w = fmaxf(w, 0.0f); h = fmaxf(h, 0.0f);
    float inter = __fmul_rn(w, h);
    float den   = __fadd_rn(__fadd_rn(sa, ap), -inter);
    float v     = __fdividef(inter, den);      // iou >= 0 -> bits monotonic
    return __float_as_uint(v);
}

__device__ __forceinline__ float focal_bg(float c0, float c1) {  // cls = 0 focal
    float e  = __expf(c1 - c0);
    float pc = __fdividef(1.0f, 1.0f + e);     // 2-class softmax via sigmoid
    pc = fminf(fmaxf(pc, 1e-7f), 1.0f - 1e-7f);
    float om = 1.0f - pc;
    return 0.25f * (-__logf(pc)) * om * om;
}
__device__ __forceinline__ float focal1(float c0, float c1, int cls) {
    float z  = c0 - c1;
    float s  = (cls == 1) ? -z : z;
    float e  = __expf(-s);
    float pc = __fdividef(1.0f, 1.0f + e);
    pc = fminf(fmaxf(pc, 1e-7f), 1.0f - 1e-7f);
    float om = 1.0f - pc;
    float fl = 0.25f * (-__logf(pc)) * om * om;
    return (cls < 2) ? fl : 0.0f;
}
__device__ __forceinline__ float smooth_l1(float d) {
    float ad = fabsf(d);
    return (ad < 1.0f) ? 0.5f * d * d : ad - 0.5f;
}

// ---------------------------------------------------------------- matching + bulk focal
__global__ __launch_bounds__(256, 4)
void k_match(const float4* __restrict__ priors, const float* __restrict__ gt,
             const float4* __restrict__ conf4) {
    __shared__ float4   sbox[ON];
    __shared__ float    sarea[ON];
    __shared__ unsigned red[ON][8];
    __shared__ float    swf[8];

    const int b = blockIdx.y, cx = blockIdx.x, tid = threadIdx.x;
    if (b == 0 && cx == 0 && tid == 0) g_ctr = 0;    // reset k_loss counter
    if (tid < ON) {
        const float* g = gt + (b * ON + tid) * 5;
        float4 v = make_float4(g[0], g[1], g[2], g[3]);
        sbox[tid]  = v;
        sarea[tid] = __fmul_rn(__fadd_rn(v.z, -v.x), __fadd_rn(v.w, -v.y));
    }
    __syncthreads();

    unsigned bo[ON];
#pragma unroll
    for (int o = 0; o < ON; o++) bo[o] = 0u;

    const int p0 = cx * CH;
#pragma unroll 1
    for (int i = tid; i < CH / 2; i += 256) {
        int pA = p0 + i;
        int pB = pA + CH / 2;
        if (pB > PN - 1) pB = PN - 1;       // tail: duplicate evals, same value written
        float4 prA = __ldg(&priors[pA]);
        float4 prB = __ldg(&priors[pB]);
        float ax0, ay0, ax1, ay1, aA; corners(prA, ax0, ay0, ax1, ay1, aA);
        float bx0, by0, bx1, by1, aB; corners(prB, bx0, by0, bx1, by1, aB);

        unsigned mvA = 0u, mvB = 0u;
#pragma unroll
        for (int o = 0; o < ON; o++) {
            float4 t  = sbox[o];
            float  sa = sarea[o];
            unsigned vA = iou_bits(ax0, ay0, ax1, ay1, aA, t, sa);
            unsigned vB = iou_bits(bx0, by0, bx1, by1, aB, t, sa);
            mvA = max(mvA, vA);
            mvB = max(mvB, vB);
            bo[o] = max(bo[o], max(vA, vB));
        }
        g_match[b * PN + pA] = (unsigned char)(mvA >= HB);
        g_match[b * PN + pB] = (unsigned char)(mvB >= HB);
    }

    // ---- bulk focal (cls=0) over this chunk's priors: DRAM is idle here ----
    // 8 priors/thread; one float4 = conf of 2 consecutive priors. PN even and
    // p even => a float4 is either fully valid (p < PN) or fully skipped.
    float fa = 0.0f;
    {
        const int myp = p0 + tid * 8;
        const float4* cb4 = conf4 + ((long long)b * PN + myp) / 2;
#pragma unroll
        for (int k = 0; k < 4; k++) {
            int p = myp + 2 * k;
            if (p < PN) {
                float4 c = __ldg(&cb4[k]);
                fa += focal_bg(c.x, c.y) + focal_bg(c.z, c.w);
            }
        }
    }

    const int lane = tid & 31, wid = tid >> 5;
#pragma unroll
    for (int o = 0; o < ON; o++) {
        unsigned m = __reduce_max_sync(0xFFFFFFFFu, bo[o]);
        if (lane == 0) red[o][wid] = m;
    }
#pragma unroll
    for (int off = 16; off; off >>= 1) fa += __shfl_down_sync(0xFFFFFFFFu, fa, off);
    if (lane == 0) swf[wid] = fa;
    __syncthreads();
    if (tid < ON) {
        unsigned m = red[tid][0];
#pragma unroll
        for (int w = 1; w < 8; w++) m = max(m, red[tid][w]);
        g_blockbo[(b * NCH + cx) * ON + tid] = m;
    }
    if (tid == 0) {
        float t = 0.0f;
#pragma unroll
        for (int w = 0; w < 8; w++) t += swf[w];
        g_pf[b * NCH + cx] = t;
    }
}

// ---------------------------------------------------------------- find best prior per (b,o): parallel rescan
__global__ __launch_bounds__(256)
void k_findp(const float4* __restrict__ priors, const float* __restrict__ gt) {
    __shared__ unsigned sred[8];
    const int bo_ = blockIdx.x;
    const int b = bo_ / ON, o = bo_ % ON;
    const int tid = threadIdx.x;

    const float* g = gt + (b * ON + o) * 5;
    float4 t  = make_float4(g[0], g[1], g[2], g[3]);
    float  sa = __fmul_rn(__fadd_rn(t.z, -t.x), __fadd_rn(t.w, -t.y));

    unsigned M = 0u; int c = 0;
#pragma unroll
    for (int cc = NCH - 1; cc >= 0; cc--) {      // descending + >= : smallest chunk wins ties
        unsigned v = g_blockbo[(b * NCH + cc) * ON + o];
        if (v >= M) { M = v; c = cc; }
    }

    unsigned minp = 0x7FFFFFFFu;
#pragma unroll
    for (int k = 0; k < CH / 256; k++) {         // 8 independent iterations -> pipelined
        int p = c * CH + k * 256 + tid;
        if (p < PN) {
            float4 pr = __ldg(&priors[p]);
            float x0, y0, x1, y1, ap; corners(pr, x0, y0, x1, y1, ap);
            if (iou_bits(x0, y0, x1, y1, ap, t, sa) == M)
                minp = min(minp, (unsigned)p);   // smallest p among ties
        }
    }
    minp = __reduce_min_sync(0xFFFFFFFFu, minp);
    if ((tid & 31) == 0) sred[tid >> 5] = minp;
    __syncthreads();
    if (tid == 0) {
        unsigned m = sred[0];
#pragma unroll
        for (int w = 1; w < 8; w++) m = min(m, sred[w]);
        if (m == 0x7FFFFFFFu) m = 0;             // safety (bit-exact => unreachable)
        g_bestp[b * ON + o] = m;
    }
}

// ---------------------------------------------------------------- override: serial per image => last-o-wins
__global__ void k_override() {
    int b = blockIdx.x, lane = threadIdx.x;
    unsigned p = (lane < ON) ? g_bestp[b * ON + lane] : 0u;
#pragma unroll
    for (int o = 0; o < ON; o++) {
        unsigned pv = __shfl_sync(0xFFFFFFFFu, p, o);
        if (lane == 0)
            g_match[b * PN + pv] = (unsigned char)((o << 2) | 3);
    }
}

// ---------------------------------------------------------------- sparse loss + device-side final reduction
__global__ __launch_bounds__(256)
void k_loss(const float4* __restrict__ loc, const float2* __restrict__ conf2,
            const float4* __restrict__ priors, const float* __restrict__ gt,
            float* __restrict__ out) {
    __shared__ float4 sbox[ON];
    __shared__ float  sarea[ON];
    __shared__ int    slab[ON];
    __shared__ unsigned short slist[CH];
    __shared__ int    scount;
    __shared__ float  swl[8], swc[8];
    __shared__ int    sIsLast;

    const int b = blockIdx.y, cx = blockIdx.x, tid = threadIdx.x;
    const int lane = tid & 31;
    if (tid == 0) { scount = 0; sIsLast = 0; }
    if (tid < ON) {
        const float* g = gt + (b * ON + tid) * 5;
        float4 v = make_float4(g[0], g[1], g[2], g[3]);
        sbox[tid]  = v;
        sarea[tid] = __fmul_rn(__fadd_rn(v.z, -v.x), __fadd_rn(v.w, -v.y));
        slab[tid]  = (int)g[4];
    }
    __syncthreads();

    const int p0 = cx * CH;

    // scan this chunk's 2048 match bytes: 2 words/thread.
    // b*PN and p0 are multiples of 4 and PN%4==0 => a word is fully valid iff p<PN.
    unsigned codes[2];
#pragma unroll
    for (int w = 0; w < 2; w++) {
        int p = p0 + (tid * 2 + w) * 4;
        codes[w] = (p < PN)
                 ? ((const unsigned*)&g_match[(long long)b * PN + p])[0] : 0u;
    }

    // single-round compaction: warp inclusive scan, <=1 smem atomic per warp
    int cnt = __popc(codes[0] & 0x01010101u) + __popc(codes[1] & 0x01010101u);
    int pre = cnt;
#pragma unroll
    for (int off = 1; off < 32; off <<= 1) {
        int v = __shfl_up_sync(0xFFFFFFFFu, pre, off);
        if (lane >= off) pre += v;
    }
    int wtotal = __shfl_sync(0xFFFFFFFFu, pre, 31);
    if (wtotal) {
        int wbase = 0;
        if (lane == 31) wbase = atomicAdd(&scount, wtotal);
        wbase = __shfl_sync(0xFFFFFFFFu, wbase, 31);
        int mybase = wbase + pre - cnt;
        if (cnt) {
            int wr = 0;
#pragma unroll
            for (int w = 0; w < 2; w++)
#pragma unroll
                for (int k = 0; k < 4; k++)
                    if ((codes[w] >> (8 * k)) & 1)
                        slist[mybase + wr++] = (unsigned short)((tid * 2 + w) * 4 + k);
        }
    }
    __syncthreads();
    const int n = scount;

    // dense over compacted positives: idx recovery + smooth-L1 + focal correction
    float sl = 0.0f, sc = 0.0f;
#pragma unroll 1
    for (int i = tid; i < n; i += 256) {
        int off = slist[i];
        int p   = p0 + off;
        long long ix = (long long)b * PN + p;
        unsigned char code = g_match[ix];
        float4 pr = __ldg(&priors[p]);
        int idx;
        if (code & 2) {
            idx = code >> 2;                       // overridden: forced GT
        } else {
            // bit-exact argmax recovery (first-o wins on ties)
            float x0, y0, x1, y1, ap; corners(pr, x0, y0, x1, y1, ap);
            unsigned best = 0u; idx = 0;
#pragma unroll
            for (int o = 0; o < ON; o++) {
                unsigned v = iou_bits(x0, y0, x1, y1, ap, sbox[o], sarea[o]);
                if (v > best) { best = v; idx = o; }
            }
        }
        int cls = slab[idx] + 1;

        // focal correction: replace the cls=0 base term with the true class
        float2 cd = __ldg(&conf2[ix]);
        sc += focal1(cd.x, cd.y, cls) - focal_bg(cd.x, cd.y);

        float4 mb = sbox[idx];
        float4 ld = __ldg(&loc[ix]);
        float iw = __fdividef(1.0f, pr.z);
        float ih = __fdividef(1.0f, pr.w);
        float gx = ((mb.x + mb.z) * 0.5f - pr.x) * 10.0f * iw;
        float gy = ((mb.y + mb.w) * 0.5f - pr.y) * 10.0f * ih;
        float gw = __logf((mb.z - mb.x) * iw) * 5.0f;
        float gh = __logf((mb.w - mb.y) * ih) * 5.0f;
        sl += smooth_l1(ld.x - gx) + smooth_l1(ld.y - gy)
            + smooth_l1(ld.z - gw) + smooth_l1(ld.w - gh);
    }

    // block reduction -> plain stores to per-block slots
#pragma unroll
    for (int off = 16; off; off >>= 1) {
        sl += __shfl_down_sync(0xFFFFFFFFu, sl, off);
        sc += __shfl_down_sync(0xFFFFFFFFu, sc, off);
    }
    if (lane == 0) { swl[tid >> 5] = sl; swc[tid >> 5] = sc; }
    __syncthreads();
    if (tid == 0) {
        float tl = 0.0f, tc = 0.0f;
#pragma unroll
        for (int w = 0; w < 8; w++) { tl += swl[w]; tc += swc[w]; }
        int slot = b * NCH + cx;
        g_pl[slot] = tl;
        g_pc[slot] = tc;
        g_pn[slot] = n;
        __threadfence();
        unsigned done = atomicAdd(&g_ctr, 1u);
        sIsLast = (done == NPART - 1);
    }
    __syncthreads();

    // last block: reduce all partials (fixed slot order => deterministic)
    if (sIsLast) {
        double dl = 0.0, dc = 0.0; int dn = 0;
        for (int i = tid; i < NPART; i += 256) {
            dl += (double)__ldcg(&g_pl[i]);
            dc += (double)__ldcg(&g_pc[i]) + (double)__ldcg(&g_pf[i]);
            dn += __ldcg(&g_pn[i]);
        }
#pragma unroll
        for (int off = 16; off; off >>= 1) {
            dl += __shfl_down_sync(0xFFFFFFFFu, dl, off);
            dc += __shfl_down_sync(0xFFFFFFFFu, dc, off);
            dn += __shfl_down_sync(0xFFFFFFFFu, dn, off);
        }
        __shared__ double sdl[8], sdc[8];
        __shared__ int    sdn[8];
        if (lane == 0) { sdl[tid >> 5] = dl; sdc[tid >> 5] = dc; sdn[tid >> 5] = dn; }
        __syncthreads();
        if (tid == 0) {
            double tl = 0.0, tc = 0.0; int tn = 0;
#pragma unroll
            for (int w = 0; w < 8; w++) { tl += sdl[w]; tc += sdc[w]; tn += sdn[w]; }
            double np = (double)tn;
            if (np < 1.0) np = 1.0;
            out[0] = (float)(tl / np);
            out[1] = (float)(tc / np);
        }
    }
}

// ---------------------------------------------------------------- launch (4 graph nodes)
extern "C" void kernel_launch(void* const* d_in, const int* in_sizes, int n_in,
                              void* d_out, int out_size) {
    const float4* loc    = (const float4*)d_in[0];  // [B,P,4] f32
    const float4* conf4  = (const float4*)d_in[1];  // [B,P,2] f32 as float4 pairs
    const float2* conf2  = (const float2*)d_in[1];  // same buffer, float2 view
    const float4* priors = (const float4*)d_in[2];  // [P,4]   f32
    const float*  gt     = (const float*)d_in[3];   // [B,O,5] f32

    dim3 gm(NCH, BN);                       // 1536 blocks: IoU matching + bulk focal
    k_match<<<gm, 256>>>(priors, gt, conf4);

    k_findp<<<BN * ON, 256>>>(priors, gt);  // 2560 blocks, parallel rescan

    k_override<<<BN, 32>>>();               // 128 warps, last-o-wins

    dim3 gl(NCH, BN);                       // 1536 blocks; last one writes d_out
    k_loss<<<gl, 256>>>(loc, conf2, priors, gt, (float*)d_out);
}

// round 17
// speedup vs baseline: 1.5401x; 1.0269x over previous
// MultiBoxLoss GB300 - R17.
// R16 post-mortem: k_loss stuck at 25.7us (issue 29%) despite tiny input; suspects
// are 1536 serialized same-address completion atomics, multi-wave short blocks, and
// low-MLP sparse gathers. This round: 3 launches total. k_match reverts to the pure
// proven 45.4us R8 core. k_loss becomes one block per image (grid=128, single wave):
// sequential conf stream (bulk focal) + thread-0 override + deterministic block-scan
// compaction + dense positives + 128-slot device-side final reduce.
// Prediction: k_loss ~5-6us, total ~55-58us.

#include <cuda_runtime.h>

#define BN 128
#define PN 24564
#define ON 20
#define NCH 12
#define CH 2048            // k_match chunk: 12*2048 = 24576 >= PN (tail clamped)
#define NW (PN / 4)        // 6141 match words per image
#define SCAP 4096          // slist capacity (expected ~480 positives/image)
#define HB 0x3F000000u     // bits of 0.5f

// ---- scratch (static device globals; all fully rewritten every call) ----
__device__ unsigned      g_blockbo[BN * NCH * ON]; // per-(b,chunk,o) max iou bits
__device__ unsigned      g_bestp[BN * ON];         // per-(b,o) best prior index
__device__ unsigned char g_match[BN * PN];         // bit0=pos, bit1=override, bits2+=idx(ovr)
__device__ float         g_pl[BN], g_pc[BN];       // per-image partial losses
__device__ int           g_pn[BN];                 // per-image positive counts
__device__ unsigned      g_ctr;                    // k_loss completion counter

// ---- bit-deterministic IoU (shared by all kernels) ----
// _rn intrinsics block FFMA contraction => identical SASS DAG everywhere.
__device__ __forceinline__ void corners(float4 pr, float& x0, float& y0,
                                        float& x1, float& y1, float& ap) {
    float hx = __fmul_rn(pr.z, 0.5f), hy = __fmul_rn(pr.w, 0.5f);
    x0 = __fadd_rn(pr.x, -hx); y0 = __fadd_rn(pr.y, -hy);
    x1 = __fadd_rn(pr.x,  hx); y1 = __fadd_rn(pr.y,  hy);
    ap = __fmul_rn(__fadd_rn(x1, -x0), __fadd_rn(y1, -y0));
}
__device__ __forceinline__ unsigned iou_bits(float x0, float y0, float x1, float y1,
                                             float ap, float4 t, float sa) {
    float w = __fadd_rn(fminf(t.z, x1), -fmaxf(t.x, x0));
    float h = __fadd_rn(fminf(t.w, y1), -fmaxf(t.y, y0));
    w = fmaxf(w, 0.0f); h = fmaxf(h, 0.0f);
    float inter = __fmul_rn(w, h);
    float den   = __fadd_rn(__fadd_rn(sa, ap), -inter);
    float v     = __fdividef(inter, den);      // iou >= 0 -> bits monotonic
    return __float_as_uint(v);
}

__device__ __forceinline__ float focal_bg(float c0, float c1) {  // cls = 0 focal
    float e  = __expf(c1 - c0);
    float pc = __fdividef(1.0f, 1.0f + e);     // 2-class softmax via sigmoid
    pc = fminf(fmaxf(pc, 1e-7f), 1.0f - 1e-7f);
    float om = 1.0f - pc;
    return 0.25f * (-__logf(pc)) * om * om;
}
__device__ __forceinline__ float focal1(float c0, float c1, int cls) {
    float z  = c0 - c1;
    float s  = (cls == 1) ? -z : z;
    float e  = __expf(-s);
    float pc = __fdividef(1.0f, 1.0f + e);
    pc = fminf(fmaxf(pc, 1e-7f), 1.0f - 1e-7f);
    float om = 1.0f - pc;
    float fl = 0.25f * (-__logf(pc)) * om * om;
    return (cls < 2) ? fl : 0.0f;
}
__device__ __forceinline__ float smooth_l1(float d) {
    float ad = fabsf(d);
    return (ad < 1.0f) ? 0.5f * d * d : ad - 0.5f;
}

// ---------------------------------------------------------------- matching (pure R8 core, proven 45.4us)
__global__ __launch_bounds__(256, 4)
void k_match(const float4* __restrict__ priors, const float* __restrict__ gt) {
    __shared__ float4   sbox[ON];
    __shared__ float    sarea[ON];
    __shared__ unsigned red[ON][8];

    const int b = blockIdx.y, cx = blockIdx.x, tid = threadIdx.x;
    if (b == 0 && cx == 0 && tid == 0) g_ctr = 0;    // reset k_loss counter
    if (tid < ON) {
        const float* g = gt + (b * ON + tid) * 5;
        float4 v = make_float4(g[0], g[1], g[2], g[3]);
        sbox[tid]  = v;
        sarea[tid] = __fmul_rn(__fadd_rn(v.z, -v.x), __fadd_rn(v.w, -v.y));
    }
    __syncthreads();

    unsigned bo[ON];
#pragma unroll
    for (int o = 0; o < ON; o++) bo[o] = 0u;

    const int p0 = cx * CH;
#pragma unroll 1
    for (int i = tid; i < CH / 2; i += 256) {
        int pA = p0 + i;
        int pB = pA + CH / 2;
        if (pB > PN - 1) pB = PN - 1;       // tail: duplicate evals, same value written
        float4 prA = __ldg(&priors[pA]);
        float4 prB = __ldg(&priors[pB]);
        float ax0, ay0, ax1, ay1, aA; corners(prA, ax0, ay0, ax1, ay1, aA);
        float bx0, by0, bx1, by1, aB; corners(prB, bx0, by0, bx1, by1, aB);

        unsigned mvA = 0u, mvB = 0u;
#pragma unroll
        for (int o = 0; o < ON; o++) {
            float4 t  = sbox[o];
            float  sa = sarea[o];
            unsigned vA = iou_bits(ax0, ay0, ax1, ay1, aA, t, sa);
            unsigned vB = iou_bits(bx0, by0, bx1, by1, aB, t, sa);
            mvA = max(mvA, vA);
            mvB = max(mvB, vB);
            bo[o] = max(bo[o], max(vA, vB));
        }
        g_match[b * PN + pA] = (unsigned char)(mvA >= HB);
        g_match[b * PN + pB] = (unsigned char)(mvB >= HB);
    }

    const int lane = tid & 31, wid = tid >> 5;
#pragma unroll
    for (int o = 0; o < ON; o++) {
        unsigned m = __reduce_max_sync(0xFFFFFFFFu, bo[o]);
        if (lane == 0) red[o][wid] = m;
    }
    __syncthreads();
    if (tid < ON) {
        unsigned m = red[tid][0];
#pragma unroll
        for (int w = 1; w < 8; w++) m = max(m, red[tid][w]);
        g_blockbo[(b * NCH + cx) * ON + tid] = m;
    }
}

// ---------------------------------------------------------------- find best prior per (b,o): parallel rescan
__global__ __launch_bounds__(256)
void k_findp(const float4* __restrict__ priors, const float* __restrict__ gt) {
    __shared__ unsigned sred[8];
    const int bo_ = blockIdx.x;
    const int b = bo_ / ON, o = bo_ % ON;
    const int tid = threadIdx.x;

    const float* g = gt + (b * ON + o) * 5;
    float4 t  = make_float4(g[0], g[1], g[2], g[3]);
    float  sa = __fmul_rn(__fadd_rn(t.z, -t.x), __fadd_rn(t.w, -t.y));

    unsigned M = 0u; int c = 0;
#pragma unroll
    for (int cc = NCH - 1; cc >= 0; cc--) {      // descending + >= : smallest chunk wins ties
        unsigned v = g_blockbo[(b * NCH + cc) * ON + o];
        if (v >= M) { M = v; c = cc; }
    }

    unsigned minp = 0x7FFFFFFFu;
#pragma unroll
    for (int k = 0; k < CH / 256; k++) {         // 8 independent iterations -> pipelined
        int p = c * CH + k * 256 + tid;
        if (p < PN) {
            float4 pr = __ldg(&priors[p]);
            float x0, y0, x1, y1, ap; corners(pr, x0, y0, x1, y1, ap);
            if (iou_bits(x0, y0, x1, y1, ap, t, sa) == M)
                minp = min(minp, (unsigned)p);   // smallest p among ties
        }
    }
    minp = __reduce_min_sync(0xFFFFFFFFu, minp);
    if ((tid & 31) == 0) sred[tid >> 5] = minp;
    __syncthreads();
    if (tid == 0) {
        unsigned m = sred[0];
#pragma unroll
        for (int w = 1; w < 8; w++) m = min(m, sred[w]);
        if (m == 0x7FFFFFFFu) m = 0;             // safety (bit-exact => unreachable)
        g_bestp[b * ON + o] = m;
    }
}

// ---------------------------------------------------------------- per-image loss: override + focal + sparse + final
__global__ __launch_bounds__(256)
void k_loss(const float4* __restrict__ loc, const float4* __restrict__ conf4,
            const float4* __restrict__ priors, const float* __restrict__ gt,
            float* __restrict__ out) {
    __shared__ float4 sbox[ON];
    __shared__ float  sarea[ON];
    __shared__ int    slab[ON];
    __shared__ unsigned short slist[SCAP];
    __shared__ int    swcnt[8];
    __shared__ float  swl[8], swc[8];
    __shared__ int    sIsLast;

    const int b = blockIdx.x, tid = threadIdx.x;
    const int lane = tid & 31, wid = tid >> 5;
    if (tid == 0) sIsLast = 0;
    if (tid < ON) {
        const float* g = gt + (b * ON + tid) * 5;
        float4 v = make_float4(g[0], g[1], g[2], g[3]);
        sbox[tid]  = v;
        sarea[tid] = __fmul_rn(__fadd_rn(v.z, -v.x), __fadd_rn(v.w, -v.y));
        slab[tid]  = (int)g[4];
    }

    // ---- bulk focal (cls=0): stream this image's conf sequentially ----
    // one float4 = conf of 2 priors; image has PN/2 = 12282 float4s, 16B aligned.
    float sc = 0.0f;
    {
        const float4* cb = conf4 + (long long)b * (PN / 2);
#pragma unroll 4
        for (int i = tid; i < PN / 2; i += 256) {
            float4 c = __ldg(&cb[i]);
            sc += focal_bg(c.x, c.y) + focal_bg(c.z, c.w);
        }
    }

    // ---- override: serial ascending o => last-o-wins (thread 0 only) ----
    if (tid == 0) {
#pragma unroll
        for (int o = 0; o < ON; o++) {
            unsigned p = g_bestp[b * ON + o];
            g_match[(long long)b * PN + p] = (unsigned char)((o << 2) | 3);
        }
    }
    __syncthreads();   // overrides visible block-wide before the scan

    // ---- scan all match words (plain loads: same kernel wrote overrides) ----
    unsigned codes[24];
    int cnt = 0;
#pragma unroll
    for (int k = 0; k < 24; k++) {
        int i = tid + k * 256;
        unsigned w = 0u;
        if (i < NW) w = ((const unsigned*)g_match)[(long long)b * NW + i];
        codes[k] = w;
        cnt += __popc(w & 0x01010101u);
    }

    // deterministic compaction: warp inclusive scan + block scan of warp totals
    int pre = cnt;
#pragma unroll
    for (int off = 1; off < 32; off <<= 1) {
        int v = __shfl_up_sync(0xFFFFFFFFu, pre, off);
        if (lane >= off) pre += v;
    }
    if (lane == 31) swcnt[wid] = pre;
    __syncthreads();
    int wbase = 0, n = 0;
#pragma unroll
    for (int w = 0; w < 8; w++) {
        int c = swcnt[w];
        if (w < wid) wbase += c;
        n += c;
    }
    if (n > SCAP) n = SCAP;
    if (cnt) {
        int s = wbase + pre - cnt;   // this thread's exclusive base
#pragma unroll
        for (int k = 0; k < 24; k++) {
            unsigned w = codes[k];
            if (w & 0x01010101u) {
#pragma unroll
                for (int j = 0; j < 4; j++)
                    if ((w >> (8 * j)) & 1) {
                        if (s < SCAP)
                            slist[s] = (unsigned short)((tid + k * 256) * 4 + j);
                        s++;
                    }
            }
        }
    }
    __syncthreads();

    // ---- dense positives: idx recovery + smooth-L1 + focal correction ----
    float sl = 0.0f;
#pragma unroll 1
    for (int i = tid; i < n; i += 256) {
        int p = slist[i];
        long long ix = (long long)b * PN + p;
        unsigned char code = g_match[ix];          // plain load (kernel wrote it)
        float4 pr = __ldg(&priors[p]);
        int idx;
        if (code & 2) {
            idx = code >> 2;                       // overridden: forced GT
        } else {
            // bit-exact argmax recovery (first-o wins on ties)
            float x0, y0, x1, y1, ap; corners(pr, x0, y0, x1, y1, ap);
            unsigned best = 0u; idx = 0;
#pragma unroll
            for (int o = 0; o < ON; o++) {
                unsigned v = iou_bits(x0, y0, x1, y1, ap, sbox[o], sarea[o]);
                if (v > best) { best = v; idx = o; }
            }
        }
        int cls = slab[idx] + 1;

        // focal correction: replace the cls=0 base term with the true class
        const float2* conf2 = (const float2*)conf4;
        float2 cd = __ldg(&conf2[ix]);
        sc += focal1(cd.x, cd.y, cls) - focal_bg(cd.x, cd.y);

        float4 mb = sbox[idx];
        float4 ld = __ldg(&loc[ix]);
        float iw = __fdividef(1.0f, pr.z);
        float ih = __fdividef(1.0f, pr.w);
        float gx = ((mb.x + mb.z) * 0.5f - pr.x) * 10.0f * iw;
        float gy = ((mb.y + mb.w) * 0.5f - pr.y) * 10.0f * ih;
        float gw = __logf((mb.z - mb.x) * iw) * 5.0f;
        float gh = __logf((mb.w - mb.y) * ih) * 5.0f;
        sl += smooth_l1(ld.x - gx) + smooth_l1(ld.y - gy)
            + smooth_l1(ld.z - gw) + smooth_l1(ld.w - gh);
    }

    // ---- block reduction -> per-image slot (plain stores) ----
#pragma unroll
    for (int off = 16; off; off >>= 1) {
        sl += __shfl_down_sync(0xFFFFFFFFu, sl, off);
        sc += __shfl_down_sync(0xFFFFFFFFu, sc, off);
    }
    if (lane == 0) { swl[wid] = sl; swc[wid] = sc; }
    __syncthreads();
    if (tid == 0) {
        float tl = 0.0f, tc = 0.0f;
#pragma unroll
        for (int w = 0; w < 8; w++) { tl += swl[w]; tc += swc[w]; }
        g_pl[b] = tl;
        g_pc[b] = tc;
        g_pn[b] = n;
        __threadfence();
        unsigned done = atomicAdd(&g_ctr, 1u);     // only 128 of these
        sIsLast = (done == BN - 1);
    }
    __syncthreads();

    // ---- last block: reduce 128 per-image partials (fixed order) ----
    if (sIsLast) {
        double dl = 0.0, dc = 0.0; int dn = 0;
        if (tid < BN) {
            dl = (double)__ldcg(&g_pl[tid]);
            dc = (double)__ldcg(&g_pc[tid]);
            dn = __ldcg(&g_pn[tid]);
        }
#pragma unroll
        for (int off = 16; off; off >>= 1) {
            dl += __shfl_down_sync(0xFFFFFFFFu, dl, off);
            dc += __shfl_down_sync(0xFFFFFFFFu, dc, off);
            dn += __shfl_down_sync(0xFFFFFFFFu, dn, off);
        }
        __shared__ double sdl[8], sdc[8];
        __shared__ int    sdn[8];
        if (lane == 0) { sdl[wid] = dl; sdc[wid] = dc; sdn[wid] = dn; }
        __syncthreads();
        if (tid == 0) {
            double tl = 0.0, tc = 0.0; int tn = 0;
#pragma unroll
            for (int w = 0; w < 8; w++) { tl += sdl[w]; tc += sdc[w]; tn += sdn[w]; }
            double np = (double)tn;
            if (np < 1.0) np = 1.0;
            out[0] = (float)(tl / np);
            out[1] = (float)(tc / np);
        }
    }
}

// ---------------------------------------------------------------- launch (3 graph nodes)
extern "C" void kernel_launch(void* const* d_in, const int* in_sizes, int n_in,
                              void* d_out, int out_size) {
    const float4* loc    = (const float4*)d_in[0];  // [B,P,4] f32
    const float4* conf4  = (const float4*)d_in[1];  // [B,P,2] f32 as float4 pairs
    const float4* priors = (const float4*)d_in[2];  // [P,4]   f32
    const float*  gt     = (const float*)d_in[3];   // [B,O,5] f32

    dim3 gm(NCH, BN);                       // 1536 blocks, proven IoU core
    k_match<<<gm, 256>>>(priors, gt);

    k_findp<<<BN * ON, 256>>>(priors, gt);  // 2560 blocks, parallel rescan

    k_loss<<<BN, 256>>>(loc, conf4, priors, gt, (float*)d_out);  // 1 block/image
}